// round 15
// baseline (speedup 1.0000x reference)
#include <cuda_runtime.h>
#include <math.h>

#define NL    2048
#define MODES 4096
#define APL   8

// Bulk L2 prefetch (cp.async.bulk.prefetch.L2.global, fire-and-forget):
//  - lin1_w: all 32 MB (needed first)
//  - lin2_w: 72 MB head
// Total 104 MB < 126 MB L2. Issued in 16 KB chunks via the TMA engine.
#define PF_CHUNK     (16u * 1024u)
#define PF1_BLOCKS   16
#define PF1_CHUNKS   (32u * 1024u * 1024u / PF_CHUNK)   // 2048
#define PF2_BLOCKS   32
#define PF2_CHUNKS   (72u * 1024u * 1024u / PF_CHUNK)   // 4608

// Scratch (allocation-free, __device__ globals per harness rules)
__device__ float g_x3[NL];
__device__ float g_h[MODES];

__device__ __forceinline__ void l2_bulk_prefetch(const void* p, unsigned bytes) {
    asm volatile("cp.async.bulk.prefetch.L2.global [%0], %1;"
                 :: "l"(p), "r"(bytes) : "memory");
}

// Stable real part of complex tanh(x * (Sr + i*Si)) for real x, fast-fp32.
// Re tanh(a+ib) = sign(a)*(1 - e^{-4|a|}) / (1 + e^{-4|a|} + 2 cos(2b) e^{-2|a|})
__device__ __forceinline__ float re_tanh_cmul_f(float x, float Sr, float Si) {
    float a = x * Sr;
    float b = x * Si;
    float aa = fabsf(a);
    float e2 = __expf(-2.0f * aa);     // arg <= 0
    float e4 = e2 * e2;
    float num = 1.0f - e4;
    if (a < 0.0f) num = -num;
    float den = 1.0f + e4 + 2.0f * __cosf(2.0f * b) * e2;
    return __fdividef(num, den);
}

__device__ __forceinline__ float dot4(float4 w, float4 x) {
    return w.x * x.x + w.y * x.y + w.z * x.z + w.w * x.w;
}

// Stage 1 (R7 body, blocks 0..31) + bulk-prefetch arms:
//   blocks 32..47  -> lin1_w (32 MB)
//   blocks 48..79  -> lin2_w head (72 MB)
// Prefetch blocks issue a few TMA bulk-prefetch instructions and exit.
__global__ void __launch_bounds__(256) stage1_kernel(
        const float* __restrict__ model_p,
        const float* __restrict__ w0,
        const float* __restrict__ w1,
        const float* __restrict__ w2,
        const float* __restrict__ lin1_w,
        const float* __restrict__ lin2_w) {
    const int t   = threadIdx.x;   // 0..255
    const int bid = blockIdx.x;

    if (bid >= 32) {
        if (bid < 32 + PF1_BLOCKS) {
            const unsigned g = (bid - 32) * 256 + t;
            const char* base = reinterpret_cast<const char*>(lin1_w);
            for (unsigned i = g; i < PF1_CHUNKS; i += PF1_BLOCKS * 256)
                l2_bulk_prefetch(base + (size_t)i * PF_CHUNK, PF_CHUNK);
        } else {
            const unsigned g = (bid - 32 - PF1_BLOCKS) * 256 + t;
            const char* base = reinterpret_cast<const char*>(lin2_w);
            for (unsigned i = g; i < PF2_CHUNKS; i += PF2_BLOCKS * 256)
                l2_bulk_prefetch(base + (size_t)i * PF_CHUNK, PF_CHUNK);
        }
        return;
    }

    const int lane = t & 31;
    const int warp = t >> 5;        // 0..7

    __shared__ float Ssh[6];
    __shared__ float red[6][8];

    const int f = bid * 64 + (t & 63);   // 32 blocks * 64 = 2048 = NL
    float x = __ldg(&model_p[(size_t)f * MODES]);  // only column 0 matters

    const float4* v0 = reinterpret_cast<const float4*>(w0);  // 2 complex / float4
    const float4* v1 = reinterpret_cast<const float4*>(w1);
    const float4* v2 = reinterpret_cast<const float4*>(w2);

    float s0r = 0.f, s0i = 0.f, s1r = 0.f, s1i = 0.f, s2r = 0.f, s2i = 0.f;
    #pragma unroll
    for (int i = t; i < MODES / 2; i += 256) {   // 8 iters x 3 loads
        float4 c0 = __ldg(&v0[i]);
        float4 c1 = __ldg(&v1[i]);
        float4 c2 = __ldg(&v2[i]);
        s0r += c0.x + c0.z;  s0i += c0.y + c0.w;
        s1r += c1.x + c1.z;  s1i += c1.y + c1.w;
        s2r += c2.x + c2.z;  s2i += c2.y + c2.w;
    }
    float acc6[6] = {s0r, s0i, s1r, s1i, s2r, s2i};
    #pragma unroll
    for (int k = 0; k < 6; k++) {
        float s = acc6[k];
        #pragma unroll
        for (int o = 16; o > 0; o >>= 1)
            s += __shfl_xor_sync(0xffffffffu, s, o);
        if (lane == 0) red[k][warp] = s;
    }
    __syncthreads();
    if (t < 6) {
        float s = 0.f;
        #pragma unroll
        for (int w = 0; w < 8; w++) s += red[t][w];
        Ssh[t] = s;
    }
    __syncthreads();

    const float S0r = Ssh[0], S0i = Ssh[1];
    const float S1r = Ssh[2], S1i = Ssh[3];
    const float S2r = Ssh[4], S2i = Ssh[5];

    x = re_tanh_cmul_f(x, S0r, S0i);
    x = re_tanh_cmul_f(x, S1r, S1i);
    x = re_tanh_cmul_f(x, S2r, S2i);
    if (t < 64) g_x3[f] = x;   // threads 64..255 computed a duplicate; drop it
}

// Warp-per-row matvec: out[row] = act(dot(W[row,:], v) + bias[row]).
// W row-major [ROWS, COLS]. 4 independent float4 streams per lane.
// Weights single-use -> __ldcs streaming loads (keeps prefetched lines and
// the hot vector resident).
template <int COLS, bool TANH, bool SRC_X3>
__global__ void __launch_bounds__(256) matvec_kernel(
        const float* __restrict__ W,
        const float* __restrict__ bias,
        float* __restrict__ out,
        int rows) {
    const int warp = (blockIdx.x * blockDim.x + threadIdx.x) >> 5;
    const int lane = threadIdx.x & 31;
    if (warp >= rows) return;

    const float* v = SRC_X3 ? g_x3 : g_h;
    const float4* __restrict__ row = reinterpret_cast<const float4*>(W + (size_t)warp * COLS);
    const float4* __restrict__ v4  = reinterpret_cast<const float4*>(v);

    constexpr int N4 = COLS / 4;   // 512 (lin1) or 1024 (lin2)
    float acc0 = 0.0f, acc1 = 0.0f, acc2 = 0.0f, acc3 = 0.0f;
    #pragma unroll
    for (int base = 0; base < N4; base += 128) {
        int i0 = base + lane;
        float4 w0 = __ldcs(&row[i0]);
        float4 w1 = __ldcs(&row[i0 + 32]);
        float4 w2 = __ldcs(&row[i0 + 64]);
        float4 w3 = __ldcs(&row[i0 + 96]);
        float4 x0 = __ldg(&v4[i0]);
        float4 x1 = __ldg(&v4[i0 + 32]);
        float4 x2 = __ldg(&v4[i0 + 64]);
        float4 x3 = __ldg(&v4[i0 + 96]);
        acc0 += dot4(w0, x0);
        acc1 += dot4(w1, x1);
        acc2 += dot4(w2, x2);
        acc3 += dot4(w3, x3);
    }
    float acc = (acc0 + acc1) + (acc2 + acc3);
    #pragma unroll
    for (int o = 16; o > 0; o >>= 1)
        acc += __shfl_xor_sync(0xffffffffu, acc, o);

    if (lane == 0) {
        float r = acc + bias[warp];
        if (TANH) r = tanhf(r);
        if (SRC_X3) g_h[warp] = r;   // stage-2 output lives in scratch
        else        out[warp] = r;
    }
}

extern "C" void kernel_launch(void* const* d_in, const int* in_sizes, int n_in,
                              void* d_out, int out_size) {
    // metadata order: model_p, w_fft_0, w_fft_1, w_fft_2, lin1_w, lin1_b, lin2_w, lin2_b
    const float* model_p = (const float*)d_in[0];
    const float* w0      = (const float*)d_in[1];   // complex64 interleaved
    const float* w1      = (const float*)d_in[2];
    const float* w2      = (const float*)d_in[3];
    const float* lin1_w  = (const float*)d_in[4];   // (4096, 2048)
    const float* lin1_b  = (const float*)d_in[5];   // (4096,)
    const float* lin2_w  = (const float*)d_in[6];   // (16384, 4096)
    const float* lin2_b  = (const float*)d_in[7];   // (16384,)
    float* out = (float*)d_out;                     // 16384

    (void)in_sizes; (void)n_in; (void)out_size;

    // Stage1 (32 blocks) + bulk prefetch arms (48 blocks)
    stage1_kernel<<<32 + PF1_BLOCKS + PF2_BLOCKS, 256>>>(
        model_p, w0, w1, w2, lin1_w, lin2_w);

    // h = tanh(lin1_w @ x3 + lin1_b): 4096 rows x 2048 cols, warp per row
    matvec_kernel<NL, true, true><<<(MODES * 32) / 256, 256>>>(lin1_w, lin1_b, out, MODES);

    // out = lin2_w @ h + lin2_b: 16384 rows x 4096 cols, warp per row
    matvec_kernel<MODES, false, false><<<(NL * APL * 32) / 256, 256>>>(lin2_w, lin2_b, out, NL * APL);
}

// round 16
// speedup vs baseline: 1.1988x; 1.1988x over previous
#include <cuda_runtime.h>
#include <math.h>

#define NL    2048
#define MODES 4096
#define APL   8

// Prefetch arms (fire-and-forget per-line prefetch.global.L2):
//  - lin1_w: all 32 MB (needed first)
//  - lin2_w: 88 MB head
// Total 120 MB < 126 MB L2. __ldcs on consumers keeps lines resident.
#define PF1_BLOCKS   96
#define PF1_THREADS  (PF1_BLOCKS * 256)
#define PF1_LINES    (32u * 1024u * 1024u / 128u)

#define PF2_BLOCKS   192
#define PF2_THREADS  (PF2_BLOCKS * 256)
#define PF2_LINES    (88u * 1024u * 1024u / 128u)

// Scratch (allocation-free, __device__ globals per harness rules)
__device__ float g_x3[NL];
__device__ float g_h[MODES];

__device__ __forceinline__ void l2_prefetch(const void* p) {
    asm volatile("prefetch.global.L2 [%0];" :: "l"(p));
}

// Stable real part of complex tanh(x * (Sr + i*Si)) for real x, fast-fp32.
// Re tanh(a+ib) = sign(a)*(1 - e^{-4|a|}) / (1 + e^{-4|a|} + 2 cos(2b) e^{-2|a|})
__device__ __forceinline__ float re_tanh_cmul_f(float x, float Sr, float Si) {
    float a = x * Sr;
    float b = x * Si;
    float aa = fabsf(a);
    float e2 = __expf(-2.0f * aa);     // arg <= 0
    float e4 = e2 * e2;
    float num = 1.0f - e4;
    if (a < 0.0f) num = -num;
    float den = 1.0f + e4 + 2.0f * __cosf(2.0f * b) * e2;
    return __fdividef(num, den);
}

__device__ __forceinline__ float dot4(float4 w, float4 x) {
    return w.x * x.x + w.y * x.y + w.z * x.z + w.w * x.w;
}

// Stage 1 (R7 body, blocks 0..31) + prefetch arms:
//   blocks 32..127   -> lin1_w (32 MB)
//   blocks 128..319  -> lin2_w head (88 MB)
__global__ void __launch_bounds__(256) stage1_kernel(
        const float* __restrict__ model_p,
        const float* __restrict__ w0,
        const float* __restrict__ w1,
        const float* __restrict__ w2,
        const float* __restrict__ lin1_w,
        const float* __restrict__ lin2_w) {
    const int t   = threadIdx.x;   // 0..255
    const int bid = blockIdx.x;

    if (bid >= 32) {
        if (bid < 32 + PF1_BLOCKS) {
            const unsigned g = (bid - 32) * 256 + t;
            const char* base = reinterpret_cast<const char*>(lin1_w);
            for (unsigned i = g; i < PF1_LINES; i += PF1_THREADS)
                l2_prefetch(base + (size_t)i * 128);
        } else {
            const unsigned g = (bid - 32 - PF1_BLOCKS) * 256 + t;
            const char* base = reinterpret_cast<const char*>(lin2_w);
            for (unsigned i = g; i < PF2_LINES; i += PF2_THREADS)
                l2_prefetch(base + (size_t)i * 128);
        }
        return;
    }

    const int lane = t & 31;
    const int warp = t >> 5;        // 0..7

    __shared__ float Ssh[6];
    __shared__ float red[6][8];

    const int f = bid * 64 + (t & 63);   // 32 blocks * 64 = 2048 = NL
    float x = __ldg(&model_p[(size_t)f * MODES]);  // only column 0 matters

    const float4* v0 = reinterpret_cast<const float4*>(w0);  // 2 complex / float4
    const float4* v1 = reinterpret_cast<const float4*>(w1);
    const float4* v2 = reinterpret_cast<const float4*>(w2);

    float s0r = 0.f, s0i = 0.f, s1r = 0.f, s1i = 0.f, s2r = 0.f, s2i = 0.f;
    #pragma unroll
    for (int i = t; i < MODES / 2; i += 256) {   // 8 iters x 3 loads
        float4 c0 = __ldg(&v0[i]);
        float4 c1 = __ldg(&v1[i]);
        float4 c2 = __ldg(&v2[i]);
        s0r += c0.x + c0.z;  s0i += c0.y + c0.w;
        s1r += c1.x + c1.z;  s1i += c1.y + c1.w;
        s2r += c2.x + c2.z;  s2i += c2.y + c2.w;
    }
    float acc6[6] = {s0r, s0i, s1r, s1i, s2r, s2i};
    #pragma unroll
    for (int k = 0; k < 6; k++) {
        float s = acc6[k];
        #pragma unroll
        for (int o = 16; o > 0; o >>= 1)
            s += __shfl_xor_sync(0xffffffffu, s, o);
        if (lane == 0) red[k][warp] = s;
    }
    __syncthreads();
    if (t < 6) {
        float s = 0.f;
        #pragma unroll
        for (int w = 0; w < 8; w++) s += red[t][w];
        Ssh[t] = s;
    }
    __syncthreads();

    const float S0r = Ssh[0], S0i = Ssh[1];
    const float S1r = Ssh[2], S1i = Ssh[3];
    const float S2r = Ssh[4], S2i = Ssh[5];

    x = re_tanh_cmul_f(x, S0r, S0i);
    x = re_tanh_cmul_f(x, S1r, S1i);
    x = re_tanh_cmul_f(x, S2r, S2i);
    if (t < 64) g_x3[f] = x;   // threads 64..255 computed a duplicate; drop it
}

// Warp-per-row matvec: out[row] = act(dot(W[row,:], v) + bias[row]).
// W row-major [ROWS, COLS]. 4 independent float4 streams per lane.
// Weights single-use -> __ldcs streaming loads (keeps prefetched lines and
// the hot vector resident).
template <int COLS, bool TANH, bool SRC_X3>
__global__ void __launch_bounds__(256) matvec_kernel(
        const float* __restrict__ W,
        const float* __restrict__ bias,
        float* __restrict__ out,
        int rows) {
    const int warp = (blockIdx.x * blockDim.x + threadIdx.x) >> 5;
    const int lane = threadIdx.x & 31;
    if (warp >= rows) return;

    const float* v = SRC_X3 ? g_x3 : g_h;
    const float4* __restrict__ row = reinterpret_cast<const float4*>(W + (size_t)warp * COLS);
    const float4* __restrict__ v4  = reinterpret_cast<const float4*>(v);

    constexpr int N4 = COLS / 4;   // 512 (lin1) or 1024 (lin2)
    float acc0 = 0.0f, acc1 = 0.0f, acc2 = 0.0f, acc3 = 0.0f;
    #pragma unroll
    for (int base = 0; base < N4; base += 128) {
        int i0 = base + lane;
        float4 w0 = __ldcs(&row[i0]);
        float4 w1 = __ldcs(&row[i0 + 32]);
        float4 w2 = __ldcs(&row[i0 + 64]);
        float4 w3 = __ldcs(&row[i0 + 96]);
        float4 x0 = __ldg(&v4[i0]);
        float4 x1 = __ldg(&v4[i0 + 32]);
        float4 x2 = __ldg(&v4[i0 + 64]);
        float4 x3 = __ldg(&v4[i0 + 96]);
        acc0 += dot4(w0, x0);
        acc1 += dot4(w1, x1);
        acc2 += dot4(w2, x2);
        acc3 += dot4(w3, x3);
    }
    float acc = (acc0 + acc1) + (acc2 + acc3);
    #pragma unroll
    for (int o = 16; o > 0; o >>= 1)
        acc += __shfl_xor_sync(0xffffffffu, acc, o);

    if (lane == 0) {
        float r = acc + bias[warp];
        if (TANH) r = tanhf(r);
        if (SRC_X3) g_h[warp] = r;   // stage-2 output lives in scratch
        else        out[warp] = r;
    }
}

extern "C" void kernel_launch(void* const* d_in, const int* in_sizes, int n_in,
                              void* d_out, int out_size) {
    // metadata order: model_p, w_fft_0, w_fft_1, w_fft_2, lin1_w, lin1_b, lin2_w, lin2_b
    const float* model_p = (const float*)d_in[0];
    const float* w0      = (const float*)d_in[1];   // complex64 interleaved
    const float* w1      = (const float*)d_in[2];
    const float* w2      = (const float*)d_in[3];
    const float* lin1_w  = (const float*)d_in[4];   // (4096, 2048)
    const float* lin1_b  = (const float*)d_in[5];   // (4096,)
    const float* lin2_w  = (const float*)d_in[6];   // (16384, 4096)
    const float* lin2_b  = (const float*)d_in[7];   // (16384,)
    float* out = (float*)d_out;                     // 16384

    (void)in_sizes; (void)n_in; (void)out_size;

    // Stage1 (32 blocks) + prefetch arms: lin1_w 32MB + lin2_w 88MB head
    stage1_kernel<<<32 + PF1_BLOCKS + PF2_BLOCKS, 256>>>(
        model_p, w0, w1, w2, lin1_w, lin2_w);

    // h = tanh(lin1_w @ x3 + lin1_b): 4096 rows x 2048 cols, warp per row
    matvec_kernel<NL, true, true><<<(MODES * 32) / 256, 256>>>(lin1_w, lin1_b, out, MODES);

    // out = lin2_w @ h + lin2_b: 16384 rows x 4096 cols, warp per row
    matvec_kernel<MODES, false, false><<<(NL * APL * 32) / 256, 256>>>(lin2_w, lin2_b, out, NL * APL);
}

// round 17
// speedup vs baseline: 1.2474x; 1.0406x over previous
#include <cuda_runtime.h>
#include <math.h>

#define NL    2048
#define MODES 4096
#define APL   8

// Prefetch arms (fire-and-forget per-line prefetch.global.L2):
//  - lin1_w: all 32 MB (needed first)
//  - lin2_w: 64 MB head
// Total 96 MB (measured optimum; 120 MB thrashes L2). More blocks per arm
// than R14 so each block's issue loop is shorter (8 lines/thread).
#define PF1_BLOCKS   128
#define PF1_THREADS  (PF1_BLOCKS * 256)
#define PF1_LINES    (32u * 1024u * 1024u / 128u)

#define PF2_BLOCKS   256
#define PF2_THREADS  (PF2_BLOCKS * 256)
#define PF2_LINES    (64u * 1024u * 1024u / 128u)

// Scratch (allocation-free, __device__ globals per harness rules)
__device__ float g_x3[NL];
__device__ float g_h[MODES];

__device__ __forceinline__ void l2_prefetch(const void* p) {
    asm volatile("prefetch.global.L2 [%0];" :: "l"(p));
}

// Stable real part of complex tanh(x * (Sr + i*Si)) for real x, fast-fp32.
// Re tanh(a+ib) = sign(a)*(1 - e^{-4|a|}) / (1 + e^{-4|a|} + 2 cos(2b) e^{-2|a|})
__device__ __forceinline__ float re_tanh_cmul_f(float x, float Sr, float Si) {
    float a = x * Sr;
    float b = x * Si;
    float aa = fabsf(a);
    float e2 = __expf(-2.0f * aa);     // arg <= 0
    float e4 = e2 * e2;
    float num = 1.0f - e4;
    if (a < 0.0f) num = -num;
    float den = 1.0f + e4 + 2.0f * __cosf(2.0f * b) * e2;
    return __fdividef(num, den);
}

__device__ __forceinline__ float dot4(float4 w, float4 x) {
    return w.x * x.x + w.y * x.y + w.z * x.z + w.w * x.w;
}

// Stage 1 (R7 body, blocks 0..31) + prefetch arms:
//   blocks 32..159   -> lin1_w (32 MB)
//   blocks 160..415  -> lin2_w head (64 MB)
__global__ void __launch_bounds__(256) stage1_kernel(
        const float* __restrict__ model_p,
        const float* __restrict__ w0,
        const float* __restrict__ w1,
        const float* __restrict__ w2,
        const float* __restrict__ lin1_w,
        const float* __restrict__ lin2_w) {
    const int t   = threadIdx.x;   // 0..255
    const int bid = blockIdx.x;

    if (bid >= 32) {
        if (bid < 32 + PF1_BLOCKS) {
            const unsigned g = (bid - 32) * 256 + t;
            const char* base = reinterpret_cast<const char*>(lin1_w);
            for (unsigned i = g; i < PF1_LINES; i += PF1_THREADS)
                l2_prefetch(base + (size_t)i * 128);
        } else {
            const unsigned g = (bid - 32 - PF1_BLOCKS) * 256 + t;
            const char* base = reinterpret_cast<const char*>(lin2_w);
            for (unsigned i = g; i < PF2_LINES; i += PF2_THREADS)
                l2_prefetch(base + (size_t)i * 128);
        }
        return;
    }

    const int lane = t & 31;
    const int warp = t >> 5;        // 0..7

    __shared__ float Ssh[6];
    __shared__ float red[6][8];

    const int f = bid * 64 + (t & 63);   // 32 blocks * 64 = 2048 = NL
    float x = __ldg(&model_p[(size_t)f * MODES]);  // only column 0 matters

    const float4* v0 = reinterpret_cast<const float4*>(w0);  // 2 complex / float4
    const float4* v1 = reinterpret_cast<const float4*>(w1);
    const float4* v2 = reinterpret_cast<const float4*>(w2);

    float s0r = 0.f, s0i = 0.f, s1r = 0.f, s1i = 0.f, s2r = 0.f, s2i = 0.f;
    #pragma unroll
    for (int i = t; i < MODES / 2; i += 256) {   // 8 iters x 3 loads
        float4 c0 = __ldg(&v0[i]);
        float4 c1 = __ldg(&v1[i]);
        float4 c2 = __ldg(&v2[i]);
        s0r += c0.x + c0.z;  s0i += c0.y + c0.w;
        s1r += c1.x + c1.z;  s1i += c1.y + c1.w;
        s2r += c2.x + c2.z;  s2i += c2.y + c2.w;
    }
    float acc6[6] = {s0r, s0i, s1r, s1i, s2r, s2i};
    #pragma unroll
    for (int k = 0; k < 6; k++) {
        float s = acc6[k];
        #pragma unroll
        for (int o = 16; o > 0; o >>= 1)
            s += __shfl_xor_sync(0xffffffffu, s, o);
        if (lane == 0) red[k][warp] = s;
    }
    __syncthreads();
    if (t < 6) {
        float s = 0.f;
        #pragma unroll
        for (int w = 0; w < 8; w++) s += red[t][w];
        Ssh[t] = s;
    }
    __syncthreads();

    const float S0r = Ssh[0], S0i = Ssh[1];
    const float S1r = Ssh[2], S1i = Ssh[3];
    const float S2r = Ssh[4], S2i = Ssh[5];

    x = re_tanh_cmul_f(x, S0r, S0i);
    x = re_tanh_cmul_f(x, S1r, S1i);
    x = re_tanh_cmul_f(x, S2r, S2i);
    if (t < 64) g_x3[f] = x;   // threads 64..255 computed a duplicate; drop it
}

// Warp-per-row matvec: out[row] = act(dot(W[row,:], v) + bias[row]).
// W row-major [ROWS, COLS]. 4 independent float4 streams per lane.
// Weights single-use -> __ldcs streaming loads (keeps prefetched lines and
// the hot vector resident).
template <int COLS, bool TANH, bool SRC_X3>
__global__ void __launch_bounds__(256) matvec_kernel(
        const float* __restrict__ W,
        const float* __restrict__ bias,
        float* __restrict__ out,
        int rows) {
    const int warp = (blockIdx.x * blockDim.x + threadIdx.x) >> 5;
    const int lane = threadIdx.x & 31;
    if (warp >= rows) return;

    const float* v = SRC_X3 ? g_x3 : g_h;
    const float4* __restrict__ row = reinterpret_cast<const float4*>(W + (size_t)warp * COLS);
    const float4* __restrict__ v4  = reinterpret_cast<const float4*>(v);

    constexpr int N4 = COLS / 4;   // 512 (lin1) or 1024 (lin2)
    float acc0 = 0.0f, acc1 = 0.0f, acc2 = 0.0f, acc3 = 0.0f;
    #pragma unroll
    for (int base = 0; base < N4; base += 128) {
        int i0 = base + lane;
        float4 w0 = __ldcs(&row[i0]);
        float4 w1 = __ldcs(&row[i0 + 32]);
        float4 w2 = __ldcs(&row[i0 + 64]);
        float4 w3 = __ldcs(&row[i0 + 96]);
        float4 x0 = __ldg(&v4[i0]);
        float4 x1 = __ldg(&v4[i0 + 32]);
        float4 x2 = __ldg(&v4[i0 + 64]);
        float4 x3 = __ldg(&v4[i0 + 96]);
        acc0 += dot4(w0, x0);
        acc1 += dot4(w1, x1);
        acc2 += dot4(w2, x2);
        acc3 += dot4(w3, x3);
    }
    float acc = (acc0 + acc1) + (acc2 + acc3);
    #pragma unroll
    for (int o = 16; o > 0; o >>= 1)
        acc += __shfl_xor_sync(0xffffffffu, acc, o);

    if (lane == 0) {
        float r = acc + bias[warp];
        if (TANH) r = tanhf(r);
        if (SRC_X3) g_h[warp] = r;   // stage-2 output lives in scratch
        else        out[warp] = r;
    }
}

extern "C" void kernel_launch(void* const* d_in, const int* in_sizes, int n_in,
                              void* d_out, int out_size) {
    // metadata order: model_p, w_fft_0, w_fft_1, w_fft_2, lin1_w, lin1_b, lin2_w, lin2_b
    const float* model_p = (const float*)d_in[0];
    const float* w0      = (const float*)d_in[1];   // complex64 interleaved
    const float* w1      = (const float*)d_in[2];
    const float* w2      = (const float*)d_in[3];
    const float* lin1_w  = (const float*)d_in[4];   // (4096, 2048)
    const float* lin1_b  = (const float*)d_in[5];   // (4096,)
    const float* lin2_w  = (const float*)d_in[6];   // (16384, 4096)
    const float* lin2_b  = (const float*)d_in[7];   // (16384,)
    float* out = (float*)d_out;                     // 16384

    (void)in_sizes; (void)n_in; (void)out_size;

    // Stage1 (32 blocks) + prefetch arms: lin1_w 32MB + lin2_w 64MB head
    stage1_kernel<<<32 + PF1_BLOCKS + PF2_BLOCKS, 256>>>(
        model_p, w0, w1, w2, lin1_w, lin2_w);

    // h = tanh(lin1_w @ x3 + lin1_b): 4096 rows x 2048 cols, warp per row
    matvec_kernel<NL, true, true><<<(MODES * 32) / 256, 256>>>(lin1_w, lin1_b, out, MODES);

    // out = lin2_w @ h + lin2_b: 16384 rows x 4096 cols, warp per row
    matvec_kernel<MODES, false, false><<<(NL * APL * 32) / 256, 256>>>(lin2_w, lin2_b, out, NL * APL);
}